// round 5
// baseline (speedup 1.0000x reference)
#include <cuda_runtime.h>
#include <cuda_fp16.h>

namespace {

constexpr int IMW = 1024;
constexpr int IMH = 1024;
constexpr int PY  = 16;   // output rows per thread (vertical pairs)
constexpr int YB  = 4;    // blockDim.y

// ---- generic comparator machinery (float and __half2 lanes) ----
__device__ __forceinline__ float   mn(float a, float b)     { return fminf(a, b); }
__device__ __forceinline__ float   mx(float a, float b)     { return fmaxf(a, b); }
__device__ __forceinline__ __half2 mn(__half2 a, __half2 b) { return __hmin2(a, b); }
__device__ __forceinline__ __half2 mx(__half2 a, __half2 b) { return __hmax2(a, b); }

template <class T>
__device__ __forceinline__ void s2(T &a, T &b) { T t = mn(a, b); b = mx(a, b); a = t; }

// 9-comparator sort5 (Batcher sort4 + insertion chain).
template <class T>
__device__ __forceinline__ void sort5(T v[5]) {
    s2(v[0], v[1]); s2(v[2], v[3]); s2(v[0], v[2]); s2(v[1], v[3]); s2(v[1], v[2]);
    s2(v[3], v[4]); s2(v[2], v[3]); s2(v[1], v[2]); s2(v[0], v[1]);
}

// 5-comparator sort4.
template <class T>
__device__ __forceinline__ void sort4(T &a, T &b, T &c, T &d) {
    s2(a, b); s2(c, d); s2(a, c); s2(b, d); s2(b, c);
}

// Place min at m[0], max at m[K-1]; multiset preserved.
template <int K, class T>
__device__ __forceinline__ void minmaxK(T *m) {
    if constexpr ((K & 1) == 0) {
        #pragma unroll
        for (int i = 0; i < K; i += 2) s2(m[i], m[i + 1]);
        #pragma unroll
        for (int i = 2; i < K; i += 2) s2(m[0], m[i]);
        #pragma unroll
        for (int i = 1; i < K - 1; i += 2) s2(m[i], m[K - 1]);
    } else {
        #pragma unroll
        for (int i = 0; i + 1 < K; i += 2) s2(m[i], m[i + 1]);
        s2(m[K - 2], m[K - 1]);
        #pragma unroll
        for (int i = 2; i <= K - 3; i += 2) s2(m[0], m[i]);
        s2(m[0], m[K - 2]);
        #pragma unroll
        for (int i = 1; i <= K - 4; i += 2) s2(m[i], m[K - 1]);
    }
}

template <class T>
__device__ __forceinline__ T med3(T a, T b, T c) {
    return mx(mn(a, b), mn(mx(a, b), c));
}

// Median of the 13 doubly-sorted candidates.
// Preconditions: t1a<=t1b, t2a<=t2b (lane-wise).
template <class T>
__device__ __forceinline__ T median13(
    T t0a, T t0b, T t1a, T t1b, T t1c,
    T t2a, T t2b, T t2c, T t3a, T t3b, T t3c, T t4a, T t4b)
{
    T l2 = t0a, h2 = t0b; s2(l2, h2);
    T l3 = t1c, h3 = t2c; s2(l3, h3);
    T l0 = t1a, l1 = t2a, h0 = t1b, h1 = t2b;
    s2(l0, l1); s2(l0, l2); s2(l0, l3);   // l0 = min of 8 (dropped)
    s2(h0, h1); s2(h1, h2); s2(h2, h3);   // h3 = max of 8 (dropped)

    T m[7];
    m[0] = l1; m[1] = l2; m[2] = l3; m[3] = h0; m[4] = h1; m[5] = h2;
    m[6] = t3a; minmaxK<7>(m);
    m[6] = t3b; minmaxK<6>(m + 1);
    m[6] = t3c; minmaxK<5>(m + 2);
    m[6] = t4a; minmaxK<4>(m + 3);
    m[6] = t4b;
    return med3(m[4], m[5], m[6]);
}

// Exact fp32 median of one 5x5 window (round-1 proven construction).
// Cold path: only for |fp16 median| < 1e-3.
__device__ __noinline__ float median25_exact(const float* __restrict__ img, int x, int y) {
    float r[5][5];
    #pragma unroll
    for (int i = 0; i < 5; ++i) {
        const int yy = y - 2 + i;
        #pragma unroll
        for (int j = 0; j < 5; ++j) {
            const int xx = x - 2 + j;
            r[i][j] = ((unsigned)yy < (unsigned)IMH && (unsigned)xx < (unsigned)IMW)
                          ? __ldg(img + yy * IMW + xx) : 0.0f;
        }
        sort5(r[i]);
    }
    float c[5][5];
    #pragma unroll
    for (int j = 0; j < 5; ++j) {
        #pragma unroll
        for (int i = 0; i < 5; ++i) c[j][i] = r[i][j];
        sort5(c[j]);
    }
    return median13(c[0][3], c[0][4],
                    c[1][2], c[1][3], c[1][4],
                    c[2][1], c[2][2], c[2][3],
                    c[3][0], c[3][1], c[3][2],
                    c[4][0], c[4][1]);
}

__global__ void __launch_bounds__(128)
median5x5_h2_kernel(const float* __restrict__ in, float* __restrict__ out) {
    const int xp = blockIdx.x * 32 + threadIdx.x;            // x-pair index
    const int x  = xp * 2;                                   // covers columns x, x+1
    const int y0 = (blockIdx.y * YB + threadIdx.y) * PY;
    const long imgoff = (long)blockIdx.z << 20;              // 1024*1024 per image
    const float* img = in + imgoff;
    float* outp = out + imgoff;

    const bool okm = (x >= 2);          // f0 (x-2), f1 (x-1) in range (x even)
    const bool okp = (x < IMW - 2);     // f4 (x+2), f5 (x+3) in range (x even)

    // Window for pixel x is f[0..4]; for x+1 it is f[1..5].
    // half2 v[j] = (f[j], f[j+1]) -> lane0 = pixel x, lane1 = pixel x+1.
    auto load_row = [&](int yy, __half2 v[5]) {
        float f0, f1, f2, f3, f4, f5;
        if ((unsigned)yy < (unsigned)IMH) {
            const float* p = img + yy * IMW + x;
            f0 = okm ? __ldg(p - 2) : 0.0f;
            f1 = okm ? __ldg(p - 1) : 0.0f;
            f2 = __ldg(p);
            f3 = __ldg(p + 1);
            f4 = okp ? __ldg(p + 2) : 0.0f;
            f5 = okp ? __ldg(p + 3) : 0.0f;
        } else {
            f0 = f1 = f2 = f3 = f4 = f5 = 0.0f;
        }
        v[0] = __floats2half2_rn(f0, f1);
        v[1] = __floats2half2_rn(f1, f2);
        v[2] = __floats2half2_rn(f2, f3);
        v[3] = __floats2half2_rn(f3, f4);
        v[4] = __floats2half2_rn(f4, f5);
    };

    // Sorted horizontal 5-windows (half2). For pair (y, y+1):
    // r0 = y-2 (private to A), r1..r4 = common, r5 = y+3 (private to B).
    __half2 r0[5], r1[5], r2[5], r3[5], r4[5], r5[5];
    load_row(y0 - 2, r0); sort5(r0);
    load_row(y0 - 1, r1); sort5(r1);
    load_row(y0 + 0, r2); sort5(r2);
    load_row(y0 + 1, r3); sort5(r3);

    #pragma unroll
    for (int p = 0; p < PY; p += 2) {
        const int y = y0 + p;
        load_row(y + 2, r4); sort5(r4);
        load_row(y + 3, r5); sort5(r5);

        // Shared per-column sort4 of the 4 common rows.
        __half2 q[5][4];
        #pragma unroll
        for (int j = 0; j < 5; ++j) {
            q[j][0] = r1[j]; q[j][1] = r2[j]; q[j][2] = r3[j]; q[j][3] = r4[j];
            sort4(q[j][0], q[j][1], q[j][2], q[j][3]);
        }

        #pragma unroll
        for (int pix = 0; pix < 2; ++pix) {
            const __half2* rp = pix ? r5 : r0;
            const __half2 a0 = rp[0], a1 = rp[1], a2 = rp[2], a3 = rp[3], a4 = rp[4];

            // O(1) merges into the required column rank sets.
            __half2 t0a = q[0][3];
            __half2 t0b = mx(q[0][2], a0);
            __half2 t1a = q[1][2], t1b = q[1][3];
            __half2 t1c = mx(q[1][1], a1);
            __half2 t2a = q[2][1], t2b = q[2][2];
            __half2 t2c = mn(mx(a2, q[2][0]), q[2][3]);   // clamp
            __half2 t3a = q[3][0], t3b = q[3][1];
            __half2 t3c = mn(q[3][2], a3);
            __half2 t4a = q[4][0];
            __half2 t4b = mn(q[4][1], a4);

            const __half2 med = median13(t0a, t0b, t1a, t1b, t1c,
                                         t2a, t2b, t2c, t3a, t3b, t3c, t4a, t4b);

            float m0 = __low2float(med);
            float m1 = __high2float(med);
            // fp16 rel err <= 2^-11 only guaranteed in the normal range;
            // recompute tiny medians exactly (rare: ~0.3% of pixels).
            if (fabsf(m0) < 1e-3f) m0 = median25_exact(img, x,     y + pix);
            if (fabsf(m1) < 1e-3f) m1 = median25_exact(img, x + 1, y + pix);

            *reinterpret_cast<float2*>(outp + (y + pix) * IMW + x) = make_float2(m0, m1);
        }

        // Slide window down two rows (renamed away under full unroll).
        #pragma unroll
        for (int j = 0; j < 5; ++j) {
            r0[j] = r2[j]; r1[j] = r3[j]; r2[j] = r4[j]; r3[j] = r5[j];
        }
    }
}

}  // namespace

extern "C" void kernel_launch(void* const* d_in, const int* in_sizes, int n_in,
                              void* d_out, int out_size) {
    const float* x = (const float*)d_in[0];
    float* out = (float*)d_out;
    const int nimg = out_size / (IMW * IMH);   // B*C = 8
    dim3 block(32, YB, 1);
    dim3 grid(IMW / (2 * 32), IMH / (YB * PY), nimg);   // (16, 16, 8)
    median5x5_h2_kernel<<<grid, block>>>(x, out);
}

// round 6
// speedup vs baseline: 1.1947x; 1.1947x over previous
#include <cuda_runtime.h>
#include <cuda_fp16.h>

namespace {

constexpr int IMW = 1024;
constexpr int IMH = 1024;
constexpr int PY  = 8;    // output rows per thread
constexpr int YB  = 4;    // blockDim.y

// ---- comparator machinery (float scalar and __half2 SIMD lanes) ----
__device__ __forceinline__ float   mn(float a, float b)     { return fminf(a, b); }
__device__ __forceinline__ float   mx(float a, float b)     { return fmaxf(a, b); }
__device__ __forceinline__ __half2 mn(__half2 a, __half2 b) { return __hmin2(a, b); }
__device__ __forceinline__ __half2 mx(__half2 a, __half2 b) { return __hmax2(a, b); }

template <class T>
__device__ __forceinline__ void s2(T &a, T &b) { T t = mn(a, b); b = mx(a, b); a = t; }

// 9-comparator sort5.
template <class T>
__device__ __forceinline__ void sort5(T v[5]) {
    s2(v[0], v[1]); s2(v[2], v[3]); s2(v[0], v[2]); s2(v[1], v[3]); s2(v[1], v[2]);
    s2(v[3], v[4]); s2(v[2], v[3]); s2(v[1], v[2]); s2(v[0], v[1]);
}

// Full 5-comparator sort4: a<=b<=c<=d.
template <class T>
__device__ __forceinline__ void sort4(T &a, T &b, T &c, T &d) {
    s2(a, b); s2(c, d); s2(a, c); s2(b, d); s2(b, c);
}

// top-2 multiset of 5 (unordered pair). sort4 prefix + 1.
template <class T>
__device__ __forceinline__ void top2of5(T a0, T a1, T a2, T a3, T a4, T &o0, T &o1) {
    sort4(a0, a1, a2, a3); s2(a2, a4);
    o0 = a3; o1 = a4;
}
// bottom-2 multiset (unordered pair).
template <class T>
__device__ __forceinline__ void bot2of5(T a0, T a1, T a2, T a3, T a4, T &o0, T &o1) {
    sort4(a0, a1, a2, a3); s2(a1, a4);
    o0 = a0; o1 = a1;
}
// top-3 multiset; o0<=o1 guaranteed (full sort4 prefix).
template <class T>
__device__ __forceinline__ void top3of5(T a0, T a1, T a2, T a3, T a4, T &o0, T &o1, T &o2) {
    sort4(a0, a1, a2, a3); s2(a1, a4);
    o0 = a2; o1 = a3; o2 = a4;
}
// bottom-3 multiset; o0<=o1 guaranteed.
template <class T>
__device__ __forceinline__ void bot3of5(T a0, T a1, T a2, T a3, T a4, T &o0, T &o1, T &o2) {
    sort4(a0, a1, a2, a3); s2(a2, a4);
    o0 = a0; o1 = a1; o2 = a2;
}
// middle-3 multiset; o0<=o1 guaranteed. sort4 + clamp of 5th:
// mid3({s0<=s1<=s2<=s3, x}) = {s1, s2, clamp(x, s0, s3)} (exact case analysis).
template <class T>
__device__ __forceinline__ void mid3of5(T a0, T a1, T a2, T a3, T a4, T &o0, T &o1, T &o2) {
    sort4(a0, a1, a2, a3);
    o0 = a1; o1 = a2; o2 = mn(mx(a4, a0), a3);
}

// Place min at m[0], max at m[K-1]; multiset preserved.
template <int K, class T>
__device__ __forceinline__ void minmaxK(T *m) {
    if constexpr ((K & 1) == 0) {
        #pragma unroll
        for (int i = 0; i < K; i += 2) s2(m[i], m[i + 1]);
        #pragma unroll
        for (int i = 2; i < K; i += 2) s2(m[0], m[i]);
        #pragma unroll
        for (int i = 1; i < K - 1; i += 2) s2(m[i], m[K - 1]);
    } else {
        #pragma unroll
        for (int i = 0; i + 1 < K; i += 2) s2(m[i], m[i + 1]);
        s2(m[K - 2], m[K - 1]);
        #pragma unroll
        for (int i = 2; i <= K - 3; i += 2) s2(m[0], m[i]);
        s2(m[0], m[K - 2]);
        #pragma unroll
        for (int i = 1; i <= K - 4; i += 2) s2(m[i], m[K - 1]);
    }
}

template <class T>
__device__ __forceinline__ T med3(T a, T b, T c) {
    return mx(mn(a, b), mn(mx(a, b), c));
}

// Median of the 13 doubly-sorted candidates. Preconditions: t1a<=t1b, t2a<=t2b.
template <class T>
__device__ __forceinline__ T median13(
    T t0a, T t0b, T t1a, T t1b, T t1c,
    T t2a, T t2b, T t2c, T t3a, T t3b, T t3c, T t4a, T t4b)
{
    T l2 = t0a, h2 = t0b; s2(l2, h2);
    T l3 = t1c, h3 = t2c; s2(l3, h3);
    T l0 = t1a, l1 = t2a, h0 = t1b, h1 = t2b;
    s2(l0, l1); s2(l0, l2); s2(l0, l3);   // l0 = min of 8 (dropped)
    s2(h0, h1); s2(h1, h2); s2(h2, h3);   // h3 = max of 8 (dropped)

    T m[7];
    m[0] = l1; m[1] = l2; m[2] = l3; m[3] = h0; m[4] = h1; m[5] = h2;
    m[6] = t3a; minmaxK<7>(m);
    m[6] = t3b; minmaxK<6>(m + 1);
    m[6] = t3c; minmaxK<5>(m + 2);
    m[6] = t4a; minmaxK<4>(m + 3);
    m[6] = t4b;
    return med3(m[4], m[5], m[6]);
}

// Exact fp32 median of one 5x5 window. Cold path for |fp16 median| < 1e-3.
__device__ __noinline__ float median25_exact(const float* __restrict__ img, int x, int y) {
    float r[5][5];
    #pragma unroll
    for (int i = 0; i < 5; ++i) {
        const int yy = y - 2 + i;
        #pragma unroll
        for (int j = 0; j < 5; ++j) {
            const int xx = x - 2 + j;
            r[i][j] = ((unsigned)yy < (unsigned)IMH && (unsigned)xx < (unsigned)IMW)
                          ? __ldg(img + yy * IMW + xx) : 0.0f;
        }
        sort5(r[i]);
    }
    float t0a, t0b, t1a, t1b, t1c, t2a, t2b, t2c, t3a, t3b, t3c, t4a, t4b;
    top2of5(r[0][0], r[1][0], r[2][0], r[3][0], r[4][0], t0a, t0b);
    top3of5(r[0][1], r[1][1], r[2][1], r[3][1], r[4][1], t1a, t1b, t1c);
    mid3of5(r[0][2], r[1][2], r[2][2], r[3][2], r[4][2], t2a, t2b, t2c);
    bot3of5(r[0][3], r[1][3], r[2][3], r[3][3], r[4][3], t3a, t3b, t3c);
    bot2of5(r[0][4], r[1][4], r[2][4], r[3][4], r[4][4], t4a, t4b);
    return median13(t0a, t0b, t1a, t1b, t1c, t2a, t2b, t2c, t3a, t3b, t3c, t4a, t4b);
}

__global__ void __launch_bounds__(128, 8)
median5x5_h2_kernel(const float* __restrict__ in, float* __restrict__ out) {
    const int xp = blockIdx.x * 32 + threadIdx.x;            // x-pair index
    const int x  = xp * 2;                                   // covers columns x, x+1
    const int y0 = (blockIdx.y * YB + threadIdx.y) * PY;
    const long imgoff = (long)blockIdx.z << 20;              // 1024*1024 per image
    const float* img = in + imgoff;
    float* outp = out + imgoff;

    const bool okm = (x >= 2);          // f0 (x-2), f1 (x-1) valid (x even)
    const bool okp = (x < IMW - 2);     // f4 (x+2), f5 (x+3) valid (x even)

    // half2 v[j] = (f[j], f[j+1]): lane0 = pixel x window, lane1 = pixel x+1.
    auto load_row = [&](int yy, __half2 v[5]) {
        float f0, f1, f2, f3, f4, f5;
        if ((unsigned)yy < (unsigned)IMH) {
            const float* p = img + yy * IMW + x;
            f0 = okm ? __ldg(p - 2) : 0.0f;
            f1 = okm ? __ldg(p - 1) : 0.0f;
            f2 = __ldg(p);
            f3 = __ldg(p + 1);
            f4 = okp ? __ldg(p + 2) : 0.0f;
            f5 = okp ? __ldg(p + 3) : 0.0f;
        } else {
            f0 = f1 = f2 = f3 = f4 = f5 = 0.0f;
        }
        v[0] = __floats2half2_rn(f0, f1);
        v[1] = __floats2half2_rn(f1, f2);
        v[2] = __floats2half2_rn(f2, f3);
        v[3] = __floats2half2_rn(f3, f4);
        v[4] = __floats2half2_rn(f4, f5);
    };

    // Sorted horizontal 5-windows for rows y-2 .. y+1 (reused down the strip).
    __half2 r0[5], r1[5], r2[5], r3[5], r4[5];
    load_row(y0 - 2, r0); sort5(r0);
    load_row(y0 - 1, r1); sort5(r1);
    load_row(y0 + 0, r2); sort5(r2);
    load_row(y0 + 1, r3); sort5(r3);

    #pragma unroll
    for (int p = 0; p < PY; ++p) {
        const int y = y0 + p;
        load_row(y + 2, r4); sort5(r4);   // only NEW row sorted per pixel-row

        // Column rank-set extraction on the doubly-sorted matrix.
        __half2 t0a, t0b, t1a, t1b, t1c, t2a, t2b, t2c, t3a, t3b, t3c, t4a, t4b;
        top2of5(r0[0], r1[0], r2[0], r3[0], r4[0], t0a, t0b);
        top3of5(r0[1], r1[1], r2[1], r3[1], r4[1], t1a, t1b, t1c);
        mid3of5(r0[2], r1[2], r2[2], r3[2], r4[2], t2a, t2b, t2c);
        bot3of5(r0[3], r1[3], r2[3], r3[3], r4[3], t3a, t3b, t3c);
        bot2of5(r0[4], r1[4], r2[4], r3[4], r4[4], t4a, t4b);

        const __half2 med = median13(t0a, t0b, t1a, t1b, t1c,
                                     t2a, t2b, t2c, t3a, t3b, t3c, t4a, t4b);

        float m0 = __low2float(med);
        float m1 = __high2float(med);
        // fp16 rel err <= 2^-11 only in the normal range; recompute tiny
        // medians exactly (~0.3% of pixels).
        if (fabsf(m0) < 1e-3f) m0 = median25_exact(img, x,     y);
        if (fabsf(m1) < 1e-3f) m1 = median25_exact(img, x + 1, y);

        *reinterpret_cast<float2*>(outp + y * IMW + x) = make_float2(m0, m1);

        // Slide window down one row (renamed away under full unroll).
        #pragma unroll
        for (int j = 0; j < 5; ++j) {
            r0[j] = r1[j]; r1[j] = r2[j]; r2[j] = r3[j]; r3[j] = r4[j];
        }
    }
}

}  // namespace

extern "C" void kernel_launch(void* const* d_in, const int* in_sizes, int n_in,
                              void* d_out, int out_size) {
    const float* x = (const float*)d_in[0];
    float* out = (float*)d_out;
    const int nimg = out_size / (IMW * IMH);   // B*C = 8
    dim3 block(32, YB, 1);
    dim3 grid(IMW / (2 * 32), IMH / (YB * PY), nimg);   // (16, 32, 8)
    median5x5_h2_kernel<<<grid, block>>>(x, out);
}

// round 7
// speedup vs baseline: 1.6182x; 1.3545x over previous
#include <cuda_runtime.h>
#include <cuda_bf16.h>

namespace {

constexpr int IMW = 1024;
constexpr int IMH = 1024;
constexpr int PY  = 16;       // output rows per thread (processed in vertical pairs)
constexpr int YB  = 4;        // blockDim.y

__device__ __forceinline__ void s2(float &a, float &b) {
    float t = fminf(a, b);
    b = fmaxf(a, b);
    a = t;
}

// 9-comparator sort5 (Batcher sort4 + insertion chain).
__device__ __forceinline__ void sort5(float v[5]) {
    s2(v[0], v[1]); s2(v[2], v[3]); s2(v[0], v[2]); s2(v[1], v[3]); s2(v[1], v[2]);
    s2(v[3], v[4]); s2(v[2], v[3]); s2(v[1], v[2]); s2(v[0], v[1]);
}

// 5-comparator sort4.
__device__ __forceinline__ void sort4(float &a, float &b, float &c, float &d) {
    s2(a, b); s2(c, d); s2(a, c); s2(b, d); s2(b, c);
}

// Place min at m[0], max at m[K-1]; multiset preserved, middles intact.
template <int K>
__device__ __forceinline__ void minmaxK(float *m) {
    if constexpr ((K & 1) == 0) {
        #pragma unroll
        for (int i = 0; i < K; i += 2) s2(m[i], m[i + 1]);
        #pragma unroll
        for (int i = 2; i < K; i += 2) s2(m[0], m[i]);
        #pragma unroll
        for (int i = 1; i < K - 1; i += 2) s2(m[i], m[K - 1]);
    } else {
        #pragma unroll
        for (int i = 0; i + 1 < K; i += 2) s2(m[i], m[i + 1]);
        s2(m[K - 2], m[K - 1]);
        #pragma unroll
        for (int i = 2; i <= K - 3; i += 2) s2(m[0], m[i]);
        s2(m[0], m[K - 2]);
        #pragma unroll
        for (int i = 1; i <= K - 4; i += 2) s2(m[i], m[K - 1]);
    }
}

__device__ __forceinline__ float med3f(float a, float b, float c) {
    return fmaxf(fminf(a, b), fminf(fmaxf(a, b), c));
}

// Median of the 13 doubly-sorted candidates.
// Preconditions exploited: t1a<=t1b (col1), t2a<=t2b (col2).
__device__ __forceinline__ float median13(
    float t0a, float t0b,                     // col0 top2 (unordered)
    float t1a, float t1b, float t1c,          // col1 top3, t1a<=t1b
    float t2a, float t2b, float t2c,          // col2 mid3, t2a<=t2b
    float t3a, float t3b, float t3c,          // col3 bot3
    float t4a, float t4b)                     // col4 bot2
{
    // minmax of 8 = {t0a,t0b,t1a,t1b,t1c,t2a,t2b,t2c} in 8 swaps.
    float l2 = t0a, h2 = t0b; s2(l2, h2);
    float l3 = t1c, h3 = t2c; s2(l3, h3);
    float l0 = t1a, l1 = t2a, h0 = t1b, h1 = t2b;
    s2(l0, l1); s2(l0, l2); s2(l0, l3);   // l0 = min of 8 (dropped)
    s2(h0, h1); s2(h1, h2); s2(h2, h3);   // h3 = max of 8 (dropped)

    float m[7];
    m[0] = l1; m[1] = l2; m[2] = l3; m[3] = h0; m[4] = h1; m[5] = h2;
    m[6] = t3a; minmaxK<7>(m);       // middle: m[1..5]
    m[6] = t3b; minmaxK<6>(m + 1);   // middle: m[2..5]
    m[6] = t3c; minmaxK<5>(m + 2);   // middle: m[3..5]
    m[6] = t4a; minmaxK<4>(m + 3);   // middle: m[4..5]
    m[6] = t4b;
    return med3f(m[4], m[5], m[6]);
}

__global__ void __launch_bounds__(128)
median5x5_kernel(const float* __restrict__ in, float* __restrict__ out) {
    const int x  = blockIdx.x * 32 + threadIdx.x;
    const int y0 = (blockIdx.y * YB + threadIdx.y) * PY;
    const long imgoff = (long)blockIdx.z << 20;  // 1024*1024 per image
    const float* img = in + imgoff;
    float* outp = out + imgoff + x;

    const bool okm2 = (x >= 2);
    const bool okm1 = (x >= 1);
    const bool okp1 = (x <= IMW - 2);
    const bool okp2 = (x <= IMW - 3);

    auto load_row = [&](int yy, float v[5]) {
        if ((unsigned)yy < (unsigned)IMH) {
            const float* p = img + yy * IMW + x;
            v[0] = okm2 ? __ldg(p - 2) : 0.0f;
            v[1] = okm1 ? __ldg(p - 1) : 0.0f;
            v[2] = __ldg(p);
            v[3] = okp1 ? __ldg(p + 1) : 0.0f;
            v[4] = okp2 ? __ldg(p + 2) : 0.0f;
        } else {
            v[0] = v[1] = v[2] = v[3] = v[4] = 0.0f;
        }
    };

    // Sorted horizontal 5-windows. For the pair (y, y+1):
    // r0 = y-2 (private to pixel A), r1..r4 = y-1..y+2 (common), r5 = y+3 (private to B).
    float r0[5], r1[5], r2[5], r3[5], r4[5], r5[5];
    load_row(y0 - 2, r0); sort5(r0);
    load_row(y0 - 1, r1); sort5(r1);
    load_row(y0 + 0, r2); sort5(r2);
    load_row(y0 + 1, r3); sort5(r3);

    #pragma unroll
    for (int p = 0; p < PY; p += 2) {
        const int y = y0 + p;
        load_row(y + 2, r4); sort5(r4);
        load_row(y + 3, r5); sort5(r5);

        // Shared per-column sort4 of the 4 common rows.
        float q[5][4];
        #pragma unroll
        for (int j = 0; j < 5; ++j) {
            q[j][0] = r1[j]; q[j][1] = r2[j]; q[j][2] = r3[j]; q[j][3] = r4[j];
            sort4(q[j][0], q[j][1], q[j][2], q[j][3]);
        }

        // O(1) merge of each pixel's private row into the required rank sets.
        // col j keeps column-ranks: j=0:{3,4} j=1:{2,3,4} j=2:{1,2,3} j=3:{0,1,2} j=4:{0,1}.
        #pragma unroll
        for (int pix = 0; pix < 2; ++pix) {
            const float* rp = pix ? r5 : r0;
            float a0 = rp[0], a1 = rp[1], a2 = rp[2], a3 = rp[3], a4 = rp[4];

            float t0a = q[0][3];
            float t0b = fmaxf(q[0][2], a0);

            float t1a = q[1][2], t1b = q[1][3];
            float t1c = fmaxf(q[1][1], a1);

            float t2a = q[2][1], t2b = q[2][2];
            float t2c = fminf(fmaxf(a2, q[2][0]), q[2][3]);   // clamp

            float t3a = q[3][0], t3b = q[3][1];
            float t3c = fminf(q[3][2], a3);

            float t4a = q[4][0];
            float t4b = fminf(q[4][1], a4);

            float med = median13(t0a, t0b, t1a, t1b, t1c,
                                 t2a, t2b, t2c, t3a, t3b, t3c, t4a, t4b);
            outp[(y + pix) * IMW] = med;
        }

        // Slide window down two rows (renamed away under full unroll).
        #pragma unroll
        for (int j = 0; j < 5; ++j) {
            r0[j] = r2[j]; r1[j] = r3[j]; r2[j] = r4[j]; r3[j] = r5[j];
        }
    }
}

}  // namespace

extern "C" void kernel_launch(void* const* d_in, const int* in_sizes, int n_in,
                              void* d_out, int out_size) {
    const float* x = (const float*)d_in[0];
    float* out = (float*)d_out;
    const int nimg = out_size / (IMW * IMH);   // B*C = 8
    dim3 block(32, YB, 1);
    dim3 grid(IMW / 32, IMH / (YB * PY), nimg);   // (32, 16, 8)
    median5x5_kernel<<<grid, block>>>(x, out);
}

// round 8
// speedup vs baseline: 1.8031x; 1.1143x over previous
#include <cuda_runtime.h>
#include <cuda_bf16.h>

namespace {

constexpr int IMW = 1024;
constexpr int IMH = 1024;
constexpr int PY  = 16;       // output rows per thread (processed in vertical pairs)
constexpr int YB  = 4;        // blockDim.y

__device__ __forceinline__ void s2(float &a, float &b) {
    float t = fminf(a, b);
    b = fmaxf(a, b);
    a = t;
}

// 9-comparator sort5 (Batcher sort4 + insertion chain).
__device__ __forceinline__ void sort5(float v[5]) {
    s2(v[0], v[1]); s2(v[2], v[3]); s2(v[0], v[2]); s2(v[1], v[3]); s2(v[1], v[2]);
    s2(v[3], v[4]); s2(v[2], v[3]); s2(v[1], v[2]); s2(v[0], v[1]);
}

// 5-comparator sort4.
__device__ __forceinline__ void sort4(float &a, float &b, float &c, float &d) {
    s2(a, b); s2(c, d); s2(a, c); s2(b, d); s2(b, c);
}

// Place min at m[0], max at m[K-1]; multiset preserved, middles intact.
template <int K>
__device__ __forceinline__ void minmaxK(float *m) {
    if constexpr ((K & 1) == 0) {
        #pragma unroll
        for (int i = 0; i < K; i += 2) s2(m[i], m[i + 1]);
        #pragma unroll
        for (int i = 2; i < K; i += 2) s2(m[0], m[i]);
        #pragma unroll
        for (int i = 1; i < K - 1; i += 2) s2(m[i], m[K - 1]);
    } else {
        #pragma unroll
        for (int i = 0; i + 1 < K; i += 2) s2(m[i], m[i + 1]);
        s2(m[K - 2], m[K - 1]);
        #pragma unroll
        for (int i = 2; i <= K - 3; i += 2) s2(m[0], m[i]);
        s2(m[0], m[K - 2]);
        #pragma unroll
        for (int i = 1; i <= K - 4; i += 2) s2(m[i], m[K - 1]);
    }
}

__device__ __forceinline__ float med3f(float a, float b, float c) {
    return fmaxf(fminf(a, b), fminf(fmaxf(a, b), c));
}

__global__ void __launch_bounds__(128)
median5x5_kernel(const float* __restrict__ in, float* __restrict__ out) {
    const int x  = blockIdx.x * 32 + threadIdx.x;
    const int y0 = (blockIdx.y * YB + threadIdx.y) * PY;
    const long imgoff = (long)blockIdx.z << 20;  // 1024*1024 per image
    const float* img = in + imgoff;
    float* outp = out + imgoff + x;

    const bool okm2 = (x >= 2);
    const bool okm1 = (x >= 1);
    const bool okp1 = (x <= IMW - 2);
    const bool okp2 = (x <= IMW - 3);

    auto load_row = [&](int yy, float v[5]) {
        if ((unsigned)yy < (unsigned)IMH) {
            const float* p = img + yy * IMW + x;
            v[0] = okm2 ? __ldg(p - 2) : 0.0f;
            v[1] = okm1 ? __ldg(p - 1) : 0.0f;
            v[2] = __ldg(p);
            v[3] = okp1 ? __ldg(p + 1) : 0.0f;
            v[4] = okp2 ? __ldg(p + 2) : 0.0f;
        } else {
            v[0] = v[1] = v[2] = v[3] = v[4] = 0.0f;
        }
    };

    // Sorted horizontal 5-windows. For the pair (y, y+1):
    // r0 = y-2 (private to pixel A), r1..r4 = y-1..y+2 (common), r5 = y+3 (private to B).
    float r0[5], r1[5], r2[5], r3[5], r4[5], r5[5];
    load_row(y0 - 2, r0); sort5(r0);
    load_row(y0 - 1, r1); sort5(r1);
    load_row(y0 + 0, r2); sort5(r2);
    load_row(y0 + 1, r3); sort5(r3);

    #pragma unroll
    for (int p = 0; p < PY; p += 2) {
        const int y = y0 + p;
        load_row(y + 2, r4); sort5(r4);
        load_row(y + 3, r5); sort5(r5);

        // Shared per-column sort4 of the 4 common rows.
        // Resulting 4x5 q-matrix is doubly sorted: q[j][k] <= q[j+1][k].
        float q[5][4];
        #pragma unroll
        for (int j = 0; j < 5; ++j) {
            q[j][0] = r1[j]; q[j][1] = r2[j]; q[j][2] = r3[j]; q[j][3] = r4[j];
            sort4(q[j][0], q[j][1], q[j][2], q[j][3]);
        }

        // The 13 candidates per pixel split into 8 SHARED (pure q) + 5 PRIVATE.
        // Shared: t0a=q[0][3], t1a=q[1][2], t1b=q[1][3], t2a=q[2][1], t2b=q[2][2],
        //         t3a=q[3][0], t3b=q[3][1], t4a=q[4][0].
        // Forgetful stage 1 (drop min & max of these 8) is pixel-independent:
        // dropped elements have >=7 of the 13 provably above/below regardless
        // of the 5 privates. Do it ONCE per pair.
        //
        // Double-sortedness gives t0a<=t1b, t1a<=t2b, t2a<=t3b, t3a<=t4a, so
        // min-of-8 lies in {t0a,t1a,t2a,t3a} and max-of-8 in {t1b,t2b,t3b,t4a}:
        // two 3-swap trees instead of a generic 8-swap minmax.
        float g0 = q[0][3], g1 = q[1][2], g2 = q[2][1], g3 = q[3][0];   // min group
        float h0 = q[1][3], h1 = q[2][2], h2 = q[3][1], h3 = q[4][0];   // max group
        s2(g0, g1); s2(g2, g3); s2(g0, g2);   // g0 = min of 8 (dropped)
        s2(h0, h1); s2(h2, h3); s2(h1, h3);   // h3 = max of 8 (dropped)
        // Survivors (multiset of the middle 6): g1, g2, g3, h0, h1, h2.

        // Per pixel: merge private row into candidate sets, then insert the
        // 5 privates into the forgetful chain (counts identical to the
        // verified start-8/insert-5 structure).
        #pragma unroll
        for (int pix = 0; pix < 2; ++pix) {
            const float* rp = pix ? r5 : r0;
            const float a0 = rp[0], a1 = rp[1], a2 = rp[2], a3 = rp[3], a4 = rp[4];

            const float t0b = fmaxf(q[0][2], a0);                   // col0 private
            const float t1c = fmaxf(q[1][1], a1);                   // col1 private
            const float t2c = fminf(fmaxf(a2, q[2][0]), q[2][3]);   // col2 clamp
            const float t3c = fminf(q[3][2], a3);                   // col3 private
            const float t4b = fminf(q[4][1], a4);                   // col4 private

            float m[7];
            m[0] = g1; m[1] = g2; m[2] = g3; m[3] = h0; m[4] = h1; m[5] = h2;
            m[6] = t0b; minmaxK<7>(m);       // middles: m[1..5]
            m[6] = t1c; minmaxK<6>(m + 1);   // middles: m[2..5]
            m[6] = t2c; minmaxK<5>(m + 2);   // middles: m[3..5]
            m[6] = t3c; minmaxK<4>(m + 3);   // middles: m[4..5]
            m[6] = t4b;
            outp[(y + pix) * IMW] = med3f(m[4], m[5], m[6]);
        }

        // Slide window down two rows (renamed away under full unroll).
        #pragma unroll
        for (int j = 0; j < 5; ++j) {
            r0[j] = r2[j]; r1[j] = r3[j]; r2[j] = r4[j]; r3[j] = r5[j];
        }
    }
}

}  // namespace

extern "C" void kernel_launch(void* const* d_in, const int* in_sizes, int n_in,
                              void* d_out, int out_size) {
    const float* x = (const float*)d_in[0];
    float* out = (float*)d_out;
    const int nimg = out_size / (IMW * IMH);   // B*C = 8
    dim3 block(32, YB, 1);
    dim3 grid(IMW / 32, IMH / (YB * PY), nimg);   // (32, 16, 8)
    median5x5_kernel<<<grid, block>>>(x, out);
}

// round 9
// speedup vs baseline: 1.9629x; 1.0886x over previous
#include <cuda_runtime.h>
#include <cuda_bf16.h>

namespace {

constexpr int IMW = 1024;
constexpr int IMH = 1024;
constexpr int PY  = 16;       // output rows per thread (processed in vertical pairs)
constexpr int YB  = 4;        // blockDim.y

__device__ __forceinline__ void s2(float &a, float &b) {
    float t = fminf(a, b);
    b = fmaxf(a, b);
    a = t;
}

// 9-comparator sort5 (Batcher sort4 + insertion chain).
__device__ __forceinline__ void sort5(float v[5]) {
    s2(v[0], v[1]); s2(v[2], v[3]); s2(v[0], v[2]); s2(v[1], v[3]); s2(v[1], v[2]);
    s2(v[3], v[4]); s2(v[2], v[3]); s2(v[1], v[2]); s2(v[0], v[1]);
}

// 5-comparator sort4.
__device__ __forceinline__ void sort4(float &a, float &b, float &c, float &d) {
    s2(a, b); s2(c, d); s2(a, c); s2(b, d); s2(b, c);
}

__device__ __forceinline__ float med3f(float a, float b, float c) {
    return fmaxf(fminf(a, b), fminf(fmaxf(a, b), c));
}

__global__ void __launch_bounds__(128)
median5x5_kernel(const float* __restrict__ in, float* __restrict__ out) {
    const int x  = blockIdx.x * 32 + threadIdx.x;
    const int y0 = (blockIdx.y * YB + threadIdx.y) * PY;
    const long imgoff = (long)blockIdx.z << 20;  // 1024*1024 per image
    const float* img = in + imgoff;
    float* outp = out + imgoff + x;

    const bool okm2 = (x >= 2);
    const bool okm1 = (x >= 1);
    const bool okp1 = (x <= IMW - 2);
    const bool okp2 = (x <= IMW - 3);

    auto load_row = [&](int yy, float v[5]) {
        if ((unsigned)yy < (unsigned)IMH) {
            const float* p = img + yy * IMW + x;
            v[0] = okm2 ? __ldg(p - 2) : 0.0f;
            v[1] = okm1 ? __ldg(p - 1) : 0.0f;
            v[2] = __ldg(p);
            v[3] = okp1 ? __ldg(p + 1) : 0.0f;
            v[4] = okp2 ? __ldg(p + 2) : 0.0f;
        } else {
            v[0] = v[1] = v[2] = v[3] = v[4] = 0.0f;
        }
    };

    // Sorted horizontal 5-windows. For the pair (y, y+1):
    // r0 = y-2 (private to pixel A), r1..r4 = y-1..y+2 (common), r5 = y+3 (private to B).
    float r0[5], r1[5], r2[5], r3[5], r4[5], r5[5];
    load_row(y0 - 2, r0); sort5(r0);
    load_row(y0 - 1, r1); sort5(r1);
    load_row(y0 + 0, r2); sort5(r2);
    load_row(y0 + 1, r3); sort5(r3);

    #pragma unroll
    for (int p = 0; p < PY; p += 2) {
        const int y = y0 + p;
        load_row(y + 2, r4); sort5(r4);
        load_row(y + 3, r5); sort5(r5);

        // Shared per-column sort4 of the 4 common rows (doubly sorted q).
        float q[5][4];
        #pragma unroll
        for (int j = 0; j < 5; ++j) {
            q[j][0] = r1[j]; q[j][1] = r2[j]; q[j][2] = r3[j]; q[j][3] = r4[j];
            sort4(q[j][0], q[j][1], q[j][2], q[j][3]);
        }

        // --- Shared: sort the 8 shared candidates, drop global min & max. ---
        // Candidates (with free preorders from sort4): (q21<=q22), (q30<=q31),
        // (q12<=q13), plus {q03, q40}. Batcher: pair + 2x merge(2,2) + merge(4,4).
        float A0 = q[2][1], A1 = q[2][2];
        float B0 = q[3][0], B1 = q[3][1];
        float C0 = q[1][2], C1 = q[1][3];
        float D0 = q[0][3], D1 = q[4][0];
        s2(D0, D1);
        s2(A0, B0); s2(A1, B1); s2(A1, B0);   // X = (A0,A1,B0,B1) sorted
        s2(C0, D0); s2(C1, D1); s2(C1, D0);   // Y = (C0,C1,D0,D1) sorted
        s2(A0, C0); s2(B0, D0); s2(B0, C0);   // even-merge
        s2(A1, C1); s2(B1, D1); s2(B1, C1);   // odd-merge
        s2(A1, B0); s2(B1, C0); s2(C1, D0);   // fixup
        // sorted8 = (A0,A1,B0,B1,C0,C1,D0,D1); drop ends A0, D1.
        const float sA = A1, sB = B0, sC = B1, sD = C0, sE = C1, sF = D0;

        // --- Per pixel: merge private row, then sorted-buffer forgetful chain.
        // Safety: at each drop, (#lows dropped) + (#inserts remaining) = 5 <= 5.
        #pragma unroll
        for (int pix = 0; pix < 2; ++pix) {
            const float* rp = pix ? r5 : r0;
            const float a0 = rp[0], a1 = rp[1], a2 = rp[2], a3 = rp[3], a4 = rp[4];

            const float t0b = fmaxf(q[0][2], a0);                   // col0 private
            const float t1c = fmaxf(q[1][1], a1);                   // col1 private
            const float t2c = fminf(fmaxf(a2, q[2][0]), q[2][3]);   // col2 clamp
            const float t3c = fminf(q[3][2], a3);                   // col3 private
            const float t4b = fminf(q[4][1], a4);                   // col4 private

            // Stage: sorted6 + t0b -> drop min&max: middles = sorted4 + 1 floater.
            const float f1 = fminf(fmaxf(t0b, sA), sF);
            // Stage: {sB..sE} + {f1, t1c} -> drop: middles = pair (sC,sD) + 2 floaters.
            float lo = f1, hi = t1c; s2(lo, hi);
            const float g1 = fmaxf(sB, lo);
            const float g2 = fminf(sE, hi);
            // Stage: {sC,sD} + {g1,g2,t2c} -> sort3 floaters, drop: 3 left.
            float u0 = g1, u1 = g2, u2 = t2c;
            s2(u0, u1); s2(u1, u2); s2(u0, u1);
            const float w0 = fmaxf(sC, u0);
            const float w2 = fminf(sD, u2);
            // Stage: {w0,u1,w2} + t3c -> minmax4, drop: 2 middles.
            float m0 = w0, m1 = u1, m2 = w2, m3 = t3c;
            s2(m0, m1); s2(m2, m3); s2(m0, m2); s2(m1, m3);
            // Final: med3 with last private.
            outp[(y + pix) * IMW] = med3f(m1, m2, t4b);
        }

        // Slide window down two rows (renamed away under full unroll).
        #pragma unroll
        for (int j = 0; j < 5; ++j) {
            r0[j] = r2[j]; r1[j] = r3[j]; r2[j] = r4[j]; r3[j] = r5[j];
        }
    }
}

}  // namespace

extern "C" void kernel_launch(void* const* d_in, const int* in_sizes, int n_in,
                              void* d_out, int out_size) {
    const float* x = (const float*)d_in[0];
    float* out = (float*)d_out;
    const int nimg = out_size / (IMW * IMH);   // B*C = 8
    dim3 block(32, YB, 1);
    dim3 grid(IMW / 32, IMH / (YB * PY), nimg);   // (32, 16, 8)
    median5x5_kernel<<<grid, block>>>(x, out);
}

// round 10
// speedup vs baseline: 2.0262x; 1.0323x over previous
#include <cuda_runtime.h>
#include <cuda_bf16.h>

namespace {

constexpr int IMW = 1024;
constexpr int IMH = 1024;
constexpr int PY  = 8;        // output rows per thread (processed in vertical pairs)
constexpr int YB  = 4;        // blockDim.y

__device__ __forceinline__ void s2(float &a, float &b) {
    float t = fminf(a, b);
    b = fmaxf(a, b);
    a = t;
}

// 9-comparator sort5 (Batcher sort4 + insertion chain).
__device__ __forceinline__ void sort5(float v[5]) {
    s2(v[0], v[1]); s2(v[2], v[3]); s2(v[0], v[2]); s2(v[1], v[3]); s2(v[1], v[2]);
    s2(v[3], v[4]); s2(v[2], v[3]); s2(v[1], v[2]); s2(v[0], v[1]);
}

// 5-comparator sort4.
__device__ __forceinline__ void sort4(float &a, float &b, float &c, float &d) {
    s2(a, b); s2(c, d); s2(a, c); s2(b, d); s2(b, c);
}

__device__ __forceinline__ float med3f(float a, float b, float c) {
    return fmaxf(fminf(a, b), fminf(fmaxf(a, b), c));
}

template <bool SAFE>
__device__ __forceinline__ void load_row(const float* __restrict__ img, int x, int yy,
                                         float v[5],
                                         bool okm2, bool okm1, bool okp1, bool okp2) {
    if (SAFE || (unsigned)yy < (unsigned)IMH) {
        const float* p = img + yy * IMW + x;
        v[0] = (SAFE || okm2) ? __ldg(p - 2) : 0.0f;
        v[1] = (SAFE || okm1) ? __ldg(p - 1) : 0.0f;
        v[2] = __ldg(p);
        v[3] = (SAFE || okp1) ? __ldg(p + 1) : 0.0f;
        v[4] = (SAFE || okp2) ? __ldg(p + 2) : 0.0f;
    } else {
        v[0] = v[1] = v[2] = v[3] = v[4] = 0.0f;
    }
}

template <bool SAFE>
__device__ __forceinline__ void process_strip(const float* __restrict__ img,
                                              float* __restrict__ outp,
                                              int x, int y0) {
    const bool okm2 = SAFE || (x >= 2);
    const bool okm1 = SAFE || (x >= 1);
    const bool okp1 = SAFE || (x <= IMW - 2);
    const bool okp2 = SAFE || (x <= IMW - 3);

    // Sorted horizontal 5-windows. For the pair (y, y+1):
    // r0 = y-2 (private to pixel A), r1..r4 = y-1..y+2 (common), r5 = y+3 (private B).
    float r0[5], r1[5], r2[5], r3[5], r4[5], r5[5];
    load_row<SAFE>(img, x, y0 - 2, r0, okm2, okm1, okp1, okp2); sort5(r0);
    load_row<SAFE>(img, x, y0 - 1, r1, okm2, okm1, okp1, okp2); sort5(r1);
    load_row<SAFE>(img, x, y0 + 0, r2, okm2, okm1, okp1, okp2); sort5(r2);
    load_row<SAFE>(img, x, y0 + 1, r3, okm2, okm1, okp1, okp2); sort5(r3);

    #pragma unroll
    for (int p = 0; p < PY; p += 2) {
        const int y = y0 + p;
        load_row<SAFE>(img, x, y + 2, r4, okm2, okm1, okp1, okp2); sort5(r4);
        load_row<SAFE>(img, x, y + 3, r5, okm2, okm1, okp1, okp2); sort5(r5);

        // Shared per-column sort4 of the 4 common rows (doubly sorted q).
        float q[5][4];
        #pragma unroll
        for (int j = 0; j < 5; ++j) {
            q[j][0] = r1[j]; q[j][1] = r2[j]; q[j][2] = r3[j]; q[j][3] = r4[j];
            sort4(q[j][0], q[j][1], q[j][2], q[j][3]);
        }

        // Shared: sort the 8 shared candidates (3 presorted pairs + 1 pair),
        // Batcher merge; drop global min & max -> sorted middle-6 sA..sF.
        float A0 = q[2][1], A1 = q[2][2];
        float B0 = q[3][0], B1 = q[3][1];
        float C0 = q[1][2], C1 = q[1][3];
        float D0 = q[0][3], D1 = q[4][0];
        s2(D0, D1);
        s2(A0, B0); s2(A1, B1); s2(A1, B0);   // X = (A0,A1,B0,B1) sorted
        s2(C0, D0); s2(C1, D1); s2(C1, D0);   // Y = (C0,C1,D0,D1) sorted
        s2(A0, C0); s2(B0, D0); s2(B0, C0);   // even-merge
        s2(A1, C1); s2(B1, D1); s2(B1, C1);   // odd-merge
        s2(A1, B0); s2(B1, C0); s2(C1, D0);   // fixup
        const float sA = A1, sB = B0, sC = B1, sD = C0, sE = C1, sF = D0;

        // Per pixel: merge private row, then sorted-buffer forgetful chain.
        #pragma unroll
        for (int pix = 0; pix < 2; ++pix) {
            const float* rp = pix ? r5 : r0;
            const float a0 = rp[0], a1 = rp[1], a2 = rp[2], a3 = rp[3], a4 = rp[4];

            const float t0b = fmaxf(q[0][2], a0);                   // col0 private
            const float t1c = fmaxf(q[1][1], a1);                   // col1 private
            const float t2c = fminf(fmaxf(a2, q[2][0]), q[2][3]);   // col2 clamp
            const float t3c = fminf(q[3][2], a3);                   // col3 private
            const float t4b = fminf(q[4][1], a4);                   // col4 private

            // sorted6 + t0b -> middles = sorted4 + 1 floater.
            const float f1 = fminf(fmaxf(t0b, sA), sF);
            // {sB..sE} + {f1, t1c} -> middles = (sC,sD) + 2 floaters.
            float lo = f1, hi = t1c; s2(lo, hi);
            const float g1 = fmaxf(sB, lo);
            const float g2 = fminf(sE, hi);
            // {sC,sD} + {g1,g2,t2c} -> sort3 floaters, clamp ends.
            float u0 = g1, u1 = g2, u2 = t2c;
            s2(u0, u1); s2(u1, u2); s2(u0, u1);
            const float w0 = fmaxf(sC, u0);
            const float w2 = fminf(sD, u2);
            // {w0,u1,w2} + t3c -> minmax4 middles.
            float m0 = w0, m1 = u1, m2 = w2, m3 = t3c;
            s2(m0, m1); s2(m2, m3); s2(m0, m2); s2(m1, m3);
            outp[(y + pix) * IMW] = med3f(m1, m2, t4b);
        }

        // Slide window down two rows (renamed away under full unroll).
        #pragma unroll
        for (int j = 0; j < 5; ++j) {
            r0[j] = r2[j]; r1[j] = r3[j]; r2[j] = r4[j]; r3[j] = r5[j];
        }
    }
}

__global__ void __launch_bounds__(128)
median5x5_kernel(const float* __restrict__ in, float* __restrict__ out) {
    const int x  = blockIdx.x * 32 + threadIdx.x;
    const int y0 = (blockIdx.y * YB + threadIdx.y) * PY;
    const long imgoff = (long)blockIdx.z << 20;  // 1024*1024 per image
    const float* img = in + imgoff;
    float* outp = out + imgoff + x;

    // Block-uniform branch: interior blocks (88%) take the check-free path.
    // x-safe: blockIdx.x in [1,30] -> x in [32,991], loads x-2..x+2 in range.
    // y-safe: blockIdx.y in [1,30] -> rows y0-2..y0+9 in [30,993].
    const bool safe = (blockIdx.x != 0) & (blockIdx.x != gridDim.x - 1) &
                      (blockIdx.y != 0) & (blockIdx.y != gridDim.y - 1);
    if (safe) {
        process_strip<true >(img, outp, x, y0);
    } else {
        process_strip<false>(img, outp, x, y0);
    }
}

}  // namespace

extern "C" void kernel_launch(void* const* d_in, const int* in_sizes, int n_in,
                              void* d_out, int out_size) {
    const float* x = (const float*)d_in[0];
    float* out = (float*)d_out;
    const int nimg = out_size / (IMW * IMH);   // B*C = 8
    dim3 block(32, YB, 1);
    dim3 grid(IMW / 32, IMH / (YB * PY), nimg);   // (32, 32, 8) = 8192 blocks
    median5x5_kernel<<<grid, block>>>(x, out);
}